// round 9
// baseline (speedup 1.0000x reference)
#include <cuda_runtime.h>
#include <cuda_fp16.h>
#include <cstdint>
#include <cstddef>

#define BB 128
#define TT 128
#define HH 1024
#define H3 3072
#define NBLK 128   // persistent grid (64 o-tiles x 2 b-tiles), all resident

// Scratch (static device globals -- no dynamic allocation allowed).
__device__ float  g_xp[50331648ULL];          // [T][B][3H] fp32 (192 MB)
__device__ __half g_whh[2ULL * 3 * HH * HH];  // Wh fp16 (12.6 MB)
__device__ uint8_t g_himg[2][262144];         // h images: [parity][tile(2)x128KB]
__device__ float  g_bias[2 * H3];             // xproj bias: bx+bh (r,z), bx (n)
__device__ unsigned g_bar_cnt;
__device__ unsigned g_bar_phs;

__device__ __forceinline__ uint32_t pack_h2(float x, float y) {
    __half2 h = __floats2half2_rn(x, y);
    return *reinterpret_cast<uint32_t*>(&h);
}

__device__ __forceinline__ void mma_f16(float d[4], const uint32_t a[4], const uint32_t b[2]) {
    asm volatile(
        "mma.sync.aligned.m16n8k16.row.col.f32.f16.f16.f32 "
        "{%0,%1,%2,%3}, {%4,%5,%6,%7}, {%8,%9}, {%0,%1,%2,%3};"
        : "+f"(d[0]), "+f"(d[1]), "+f"(d[2]), "+f"(d[3])
        : "r"(a[0]), "r"(a[1]), "r"(a[2]), "r"(a[3]), "r"(b[0]), "r"(b[1]));
}

__device__ __forceinline__ void ldsm4(uint32_t& r0, uint32_t& r1, uint32_t& r2, uint32_t& r3,
                                      uint32_t addr) {
    asm volatile("ldmatrix.sync.aligned.m8n8.x4.shared.b16 {%0,%1,%2,%3}, [%4];"
                 : "=r"(r0), "=r"(r1), "=r"(r2), "=r"(r3) : "r"(addr));
}

__device__ __forceinline__ void mbar_wait(uint32_t mbar, uint32_t parity) {
    asm volatile(
        "{\n\t.reg .pred P;\n\t"
        "WL_%=:\n\t"
        "mbarrier.try_wait.parity.acquire.cta.shared::cta.b64 P, [%0], %1, 0x989680;\n\t"
        "@P bra.uni WD_%=;\n\t"
        "bra.uni WL_%=;\n\t"
        "WD_%=:\n\t}"
        :: "r"(mbar), "r"(parity) : "memory");
}

// Grid barrier: all NBLK CTAs co-resident (1 per SM). Tight spin.
__device__ __forceinline__ void grid_sync_dev() {
    __syncthreads();
    if (threadIdx.x == 0) {
        volatile unsigned* vphs = &g_bar_phs;
        unsigned ph = *vphs;
        __threadfence();
        unsigned ticket = atomicAdd(&g_bar_cnt, 1u);
        if (ticket == NBLK - 1) {
            *((volatile unsigned*)&g_bar_cnt) = 0u;
            __threadfence();
            *vphs = ph + 1u;
        } else {
            while (*vphs == ph) {}
            __threadfence();
        }
    }
    __syncthreads();
}

// ---------------------------------------------------------------------------
__global__ void cvt_f16_kernel(const float* __restrict__ src, __half* __restrict__ dst, int n4)
{
    int i = blockIdx.x * blockDim.x + threadIdx.x;
    if (i < n4) {
        float4 v = ((const float4*)src)[i];
        ((uint2*)dst)[i] = make_uint2(pack_h2(v.x, v.y), pack_h2(v.z, v.w));
    }
}

// h0 (fp32 [B,H]) -> parity-0 h image (fp16, pre-swizzled smem layout).
__global__ void cvt_img_kernel(const float* __restrict__ src)
{
    int i = blockIdx.x * blockDim.x + threadIdx.x;   // chunk id, 16384 total
    int b = i >> 7, c = i & 127;
    int tile = b >> 6, row = b & 63;
    const float* s = src + (size_t)b * HH + c * 8;
    float4 v0 = ((const float4*)s)[0];
    float4 v1 = ((const float4*)s)[1];
    uint4 o;
    o.x = pack_h2(v0.x, v0.y); o.y = pack_h2(v0.z, v0.w);
    o.z = pack_h2(v1.x, v1.y); o.w = pack_h2(v1.z, v1.w);
    int p = c >> 6, c2 = c & 63;
    uint32_t off = (uint32_t)tile * 131072u + (uint32_t)p * 65536u
                 + (uint32_t)row * 1024u + (uint32_t)((c2 ^ (row & 7)) << 4);
    *(uint4*)(&g_himg[0][0] + off) = o;
}

// Combined bias for xproj: bx + bh for gates r,z ; bx only for gate n.
__global__ void bias_kernel(const float* __restrict__ bx, const float* __restrict__ bh,
                            float* __restrict__ out)
{
    int i = blockIdx.x * blockDim.x + threadIdx.x;
    if (i < 2 * H3) {
        int n = i % H3;
        float v = bx[i];
        if (n < 2 * HH) v += bh[i];
        out[i] = v;
    }
}

// ---------------------------------------------------------------------------
// xproj (fp16): C[m][n] = sum_k A[m][k]*W[n][k] + bias[n]   (validated)
// ---------------------------------------------------------------------------
#define XROW 40

__global__ __launch_bounds__(256) void xproj_kernel(
    const float* __restrict__ cur, const float* __restrict__ W,
    const float* __restrict__ bias, float* __restrict__ xp)
{
    __shared__ __half As[2][128 * XROW];
    __shared__ __half Bs[2][128 * XROW];

    const int tid  = threadIdx.x;
    const int lane = tid & 31;
    const int wid  = tid >> 5;
    const int wm   = (wid >> 2) * 64;
    const int wn   = (wid & 3) * 32;
    const int m0   = blockIdx.y * 128;
    const int n0   = blockIdx.x * 128;

    const float* gpA[4]; const float* gpB[4]; int soff[4];
    #pragma unroll
    for (int i = 0; i < 4; i++) {
        int idx = tid + i * 256;
        int row = idx >> 3, kv = idx & 7;
        int m = m0 + row;
        int b = m & (BB - 1);
        int t = m >> 7;
        gpA[i]  = cur + ((size_t)b * TT + t) * HH + kv * 4;
        gpB[i]  = W + (size_t)(n0 + row) * HH + kv * 4;
        soff[i] = row * XROW + kv * 4;
    }

    float acc[4][4][4];
    #pragma unroll
    for (int a = 0; a < 4; a++)
        #pragma unroll
        for (int b = 0; b < 4; b++)
            #pragma unroll
            for (int c = 0; c < 4; c++) acc[a][b][c] = 0.f;

    float4 ra[4], rb[4];
    #pragma unroll
    for (int i = 0; i < 4; i++) { ra[i] = *(const float4*)gpA[i]; rb[i] = *(const float4*)gpB[i]; }
    #pragma unroll
    for (int i = 0; i < 4; i++) {
        *(uint2*)&As[0][soff[i]] = make_uint2(pack_h2(ra[i].x, ra[i].y), pack_h2(ra[i].z, ra[i].w));
        *(uint2*)&Bs[0][soff[i]] = make_uint2(pack_h2(rb[i].x, rb[i].y), pack_h2(rb[i].z, rb[i].w));
    }
    __syncthreads();

    uint32_t asb[2], bsb[2];
    asb[0] = (uint32_t)__cvta_generic_to_shared(&As[0][0]);
    asb[1] = (uint32_t)__cvta_generic_to_shared(&As[1][0]);
    bsb[0] = (uint32_t)__cvta_generic_to_shared(&Bs[0][0]);
    bsb[1] = (uint32_t)__cvta_generic_to_shared(&Bs[1][0]);

    const int g  = lane >> 3;
    const int r8 = lane & 7;
    const uint32_t aRow = (uint32_t)(((g & 1) * 8 + r8) * 80 + (g >> 1) * 16);
    const uint32_t bRow = (uint32_t)(((g >> 1) * 8 + r8) * 80 + (g & 1) * 16);

    const int NKT = HH / 32;
    for (int kt = 0; kt < NKT; kt++) {
        int cb = kt & 1;
        if (kt + 1 < NKT) {
            #pragma unroll
            for (int i = 0; i < 4; i++) {
                ra[i] = *(const float4*)(gpA[i] + (kt + 1) * 32);
                rb[i] = *(const float4*)(gpB[i] + (kt + 1) * 32);
            }
        }
        #pragma unroll
        for (int kk = 0; kk < 2; kk++) {
            uint32_t kb = (uint32_t)kk * 32;
            uint32_t af[4][4], bf[2][4];
            #pragma unroll
            for (int mt = 0; mt < 4; mt++)
                ldsm4(af[mt][0], af[mt][1], af[mt][2], af[mt][3],
                      asb[cb] + (uint32_t)(wm + mt * 16) * 80 + aRow + kb);
            #pragma unroll
            for (int nb2 = 0; nb2 < 2; nb2++)
                ldsm4(bf[nb2][0], bf[nb2][1], bf[nb2][2], bf[nb2][3],
                      bsb[cb] + (uint32_t)(wn + nb2 * 16) * 80 + bRow + kb);
            #pragma unroll
            for (int mt = 0; mt < 4; mt++)
                #pragma unroll
                for (int nb2 = 0; nb2 < 2; nb2++) {
                    mma_f16(acc[mt][nb2 * 2],     af[mt], &bf[nb2][0]);
                    mma_f16(acc[mt][nb2 * 2 + 1], af[mt], &bf[nb2][2]);
                }
        }
        if (kt + 1 < NKT) {
            int nb = cb ^ 1;
            #pragma unroll
            for (int i = 0; i < 4; i++) {
                *(uint2*)&As[nb][soff[i]] = make_uint2(pack_h2(ra[i].x, ra[i].y), pack_h2(ra[i].z, ra[i].w));
                *(uint2*)&Bs[nb][soff[i]] = make_uint2(pack_h2(rb[i].x, rb[i].y), pack_h2(rb[i].z, rb[i].w));
            }
            __syncthreads();
        }
    }

    #pragma unroll
    for (int mt = 0; mt < 4; mt++) {
        int r = m0 + wm + mt * 16 + (lane >> 2);
        #pragma unroll
        for (int nt = 0; nt < 4; nt++) {
            int cg = n0 + wn + nt * 8 + (lane & 3) * 2;
            float2 bz = *(const float2*)(bias + cg);
            float2 v0 = make_float2(acc[mt][nt][0] + bz.x, acc[mt][nt][1] + bz.y);
            float2 v1 = make_float2(acc[mt][nt][2] + bz.x, acc[mt][nt][3] + bz.y);
            *(float2*)(xp + (size_t)r * H3 + cg)       = v0;
            *(float2*)(xp + (size_t)(r + 8) * H3 + cg) = v1;
        }
    }
}

// ---------------------------------------------------------------------------
// Persistent recurrence v3: h tile delivered by 2 x cp.async.bulk (64 KB) from
// a pre-swizzled global image; epilogue writes next step's image directly.
//   CTA: 64 batches x 16 units (48 B-rows = unit*3+gate). Grid (64,2)=128.
//   SMEM: [0..64) bh_n, [64..80) 2 mbarriers, Wh 48x2048B, h image 2x64KB.
// ---------------------------------------------------------------------------
#define WOFF 1024
#define HOFF (WOFF + 48 * 2048)          // 99328
#define SMEM_TOT (HOFF + 131072)         // 230400

__global__ __launch_bounds__(384) void persist_kernel(
    const __half* __restrict__ Wh_h,     // fp16 [3,H,H] (layer slice)
    const float*  __restrict__ bhn,      // [H] gate-n hidden bias
    const float*  __restrict__ h0l,      // fp32 [B,H] initial hidden
    const float*  __restrict__ xp,       // [T,B,3H]
    float*        __restrict__ y,        // [B,T,H]
    float*        __restrict__ hlast)    // fp32 [B,H] final hidden out
{
    extern __shared__ uint8_t dsm[];
    const uint32_t smbase = (uint32_t)__cvta_generic_to_shared(dsm);
    const int tid  = threadIdx.x;
    const int lane = tid & 31;
    const int wid  = tid >> 5;           // 0..11
    const int o0   = blockIdx.x * 16;    // unit base
    const int by   = blockIdx.y;         // batch tile (0/1)
    const int b0   = by * 64;
    const int wm   = (wid / 3) * 16;     // 0,16,32,48
    const int wn   = (wid % 3) * 16;     // 0,16,32

    // Header: bh_n + two mbarriers.
    if (tid < 16) ((float*)dsm)[tid] = bhn[o0 + tid];
    if (tid == 0) {
        asm volatile("mbarrier.init.shared.b64 [%0], %1;" :: "r"(smbase + 64), "r"(1u) : "memory");
        asm volatile("mbarrier.init.shared.b64 [%0], %1;" :: "r"(smbase + 72), "r"(1u) : "memory");
    }

    // One-time Wh load: 48 rows x 128 chunks(16B). Row r = 3*u + g.
    for (int i = tid; i < 6144; i += 384) {
        int r = i >> 7, c = i & 127;
        int u = r / 3, g = r - 3 * u;
        const __half* src = Wh_h + ((size_t)(g * HH + o0 + u)) * HH + c * 8;
        uint32_t dst = smbase + WOFF + (uint32_t)r * 2048 + (uint32_t)((c ^ (r & 7)) << 4);
        asm volatile("cp.async.cg.shared.global [%0], [%1], 16;" :: "r"(dst), "l"(src));
    }
    asm volatile("cp.async.commit_group;");

    // Epilogue thread mapping: b = tid>>2, u0 = (tid&3)*4.
    const int eb  = tid >> 2;
    const int eu0 = (tid & 3) * 4;
    const int ebg = b0 + eb;
    const int eog = o0 + eu0;
    // Pre-swizzled image offset for this thread's 8-byte h write.
    const uint32_t ecc  = (uint32_t)(eog >> 3);
    const uint32_t eoff = (ecc >> 6) * 65536u + (uint32_t)eb * 1024u
                        + (((ecc & 63u) ^ (uint32_t)(eb & 7)) << 4) + ((uint32_t)(eog & 4) << 1);

    // h carried in registers; init from h0 (fp32, exact).
    float hv[4] = {0.f, 0.f, 0.f, 0.f};
    if (tid < 256) {
        float4 h04 = *(const float4*)(h0l + (size_t)ebg * HH + eog);
        hv[0] = h04.x; hv[1] = h04.y; hv[2] = h04.z; hv[3] = h04.w;
    }

    asm volatile("cp.async.wait_group 0;");
    __syncthreads();

    // Invariant ldsm per-lane bases.
    const int g  = lane >> 3;
    const int r8 = lane & 7;
    const int arow = wm + (g & 1) * 8 + r8;          // h row (batch)
    const int brow = wn + (g >> 1) * 8 + r8;         // Wh row
    const uint32_t aBase0 = smbase + HOFF + (uint32_t)arow * 1024;
    const uint32_t bBase  = smbase + WOFF + (uint32_t)brow * 2048;
    const uint32_t arm = (uint32_t)(arow & 7);
    const uint32_t brm = (uint32_t)(brow & 7);
    const uint32_t ahalf = (uint32_t)(g >> 1);
    const uint32_t bhalf = (uint32_t)(g & 1);

    for (int t = 0; t < TT; t++) {
        // Issue both 64 KB bulk copies of this step's h image.
        if (tid == 0) {
            const uint8_t* src = &g_himg[t & 1][0] + (uint32_t)by * 131072u;
            #pragma unroll
            for (int p = 0; p < 2; p++) {
                uint32_t mb = smbase + 64 + (uint32_t)p * 8;
                asm volatile("mbarrier.arrive.expect_tx.shared.b64 _, [%0], %1;"
                             :: "r"(mb), "r"(65536u) : "memory");
                asm volatile(
                    "cp.async.bulk.shared::cta.global.mbarrier::complete_tx::bytes "
                    "[%0], [%1], %2, [%3];"
                    :: "r"(smbase + HOFF + (uint32_t)p * 65536u),
                       "l"(src + p * 65536), "r"(65536u), "r"(mb) : "memory");
            }
        }

        // Prefetch xp for this step's epilogue (hidden under the GEMM).
        float4 xr4, xz4, xn4;
        if (tid < 256) {
            const float* xpr = xp + (size_t)t * BB * H3 + (size_t)ebg * H3 + eog;
            xr4 = *(const float4*)(xpr);
            xz4 = *(const float4*)(xpr + HH);
            xn4 = *(const float4*)(xpr + 2 * HH);
        }

        float acc[2][4];
        #pragma unroll
        for (int nt = 0; nt < 2; nt++)
            #pragma unroll
            for (int c = 0; c < 4; c++) acc[nt][c] = 0.f;

        // Mainloop: 2 phases x 32 K16. Phase p gated by its mbarrier.
        #pragma unroll 1
        for (int p = 0; p < 2; p++) {
            mbar_wait(smbase + 64 + (uint32_t)p * 8, (uint32_t)(t & 1));
            const uint32_t aB = aBase0 + (uint32_t)p * 65536u;
            #pragma unroll
            for (int kk = 0; kk < 32; kk++) {
                uint32_t q   = 2u * (uint32_t)kk + ahalf;           // local h chunk
                uint32_t cbk = 2u * (uint32_t)(p * 32 + kk) + bhalf; // Wh chunk
                uint32_t af[4], bf[4];
                ldsm4(af[0], af[1], af[2], af[3], aB + ((q ^ arm) << 4));
                ldsm4(bf[0], bf[1], bf[2], bf[3], bBase + ((cbk ^ brm) << 4));
                mma_f16(acc[0], af, &bf[0]);
                mma_f16(acc[1], af, &bf[2]);
            }
        }
        __syncthreads();   // fragment reads done -> safe to alias h region

        // Scatter accumulators: Cs[64][52] fp32, aliased onto h region.
        float* Cs = (float*)(dsm + HOFF);
        #pragma unroll
        for (int nt = 0; nt < 2; nt++) {
            int r = wm + (lane >> 2);
            int c = wn + nt * 8 + (lane & 3) * 2;
            Cs[r * 52 + c]           = acc[nt][0];
            Cs[r * 52 + c + 1]       = acc[nt][1];
            Cs[(r + 8) * 52 + c]     = acc[nt][2];
            Cs[(r + 8) * 52 + c + 1] = acc[nt][3];
        }
        __syncthreads();

        // Gate fusion: h in registers; write y + next-parity h image.
        if (tid < 256) {
            const float* bhn_s = (const float*)dsm;
            #pragma unroll
            for (int j = 0; j < 4; j++) {
                int u = eu0 + j;
                float hr = Cs[eb * 52 + 3 * u + 0];
                float hz = Cs[eb * 52 + 3 * u + 1];
                float hn = Cs[eb * 52 + 3 * u + 2] + bhn_s[u];
                float r  = 1.f / (1.f + __expf(-(((const float*)&xr4)[j] + hr)));
                float z  = 1.f / (1.f + __expf(-(((const float*)&xz4)[j] + hz)));
                float n  = tanhf(((const float*)&xn4)[j] + r * hn);
                hv[j] = (1.f - z) * n + z * hv[j];
            }
            *(float4*)(y + ((size_t)ebg * TT + t) * HH + eog) =
                make_float4(hv[0], hv[1], hv[2], hv[3]);
            uint8_t* dimg = &g_himg[(t + 1) & 1][0] + (uint32_t)by * 131072u + eoff;
            *(uint2*)dimg = make_uint2(pack_h2(hv[0], hv[1]), pack_h2(hv[2], hv[3]));
            if (t == TT - 1)
                *(float4*)(hlast + (size_t)ebg * HH + eog) =
                    make_float4(hv[0], hv[1], hv[2], hv[3]);
        }

        if (t + 1 < TT) grid_sync_dev();
    }

    __syncthreads();
    if (tid == 0) {
        asm volatile("mbarrier.inval.shared.b64 [%0];" :: "r"(smbase + 64) : "memory");
        asm volatile("mbarrier.inval.shared.b64 [%0];" :: "r"(smbase + 72) : "memory");
    }
}

// ---------------------------------------------------------------------------
extern "C" void kernel_launch(void* const* d_in, const int* in_sizes, int n_in,
                              void* d_out, int out_size)
{
    (void)in_sizes; (void)n_in; (void)out_size;
    const float* x   = (const float*)d_in[0];  // [B,T,H]
    const float* h0  = (const float*)d_in[1];  // [L,B,H]
    const float* Wx  = (const float*)d_in[2];  // [L,3,H,H]
    const float* Wh  = (const float*)d_in[3];  // [L,3,H,H]
    const float* bx  = (const float*)d_in[4];  // [L,3,H]
    const float* bh  = (const float*)d_in[5];  // [L,3,H]
    float* out   = (float*)d_out;              // [B,T,H] then [L,B,H]
    float* hlast = out + (size_t)BB * TT * HH;

    float*  xp  = nullptr;
    __half* whh = nullptr;
    float*  gb  = nullptr;
    cudaGetSymbolAddress((void**)&xp,  g_xp);
    cudaGetSymbolAddress((void**)&whh, g_whh);
    cudaGetSymbolAddress((void**)&gb,  g_bias);

    cudaFuncSetAttribute(persist_kernel,
                         cudaFuncAttributeMaxDynamicSharedMemorySize, SMEM_TOT);

    // Pre-convert Wh to fp16; build combined xproj bias.
    {
        int n4 = 2 * 3 * HH * HH / 4;
        cvt_f16_kernel<<<n4 / 256, 256>>>(Wh, whh, n4);
        bias_kernel<<<(2 * H3 + 255) / 256, 256>>>(bx, bh, gb);
    }

    dim3 xgrid(H3 / 128, (BB * TT) / 128);  // (24, 128)
    dim3 pgrid(64, 2);                      // 128 CTAs

    for (int l = 0; l < 2; l++) {
        const float* cur = (l == 0) ? x : out;  // layer-1 input = layer-0 output
        xproj_kernel<<<xgrid, 256>>>(cur, Wx + (size_t)l * 3 * HH * HH,
                                     gb + (size_t)l * H3, xp);
        cvt_img_kernel<<<64, 256>>>(h0 + (size_t)l * BB * HH);
        persist_kernel<<<pgrid, 384, SMEM_TOT>>>(
            whh + (size_t)l * 3 * HH * HH,
            bh + (size_t)l * H3 + 2 * HH,      // bh_n
            h0 + (size_t)l * BB * HH,
            xp, out,
            hlast + (size_t)l * BB * HH);
    }
}

// round 10
// speedup vs baseline: 1.0407x; 1.0407x over previous
#include <cuda_runtime.h>
#include <cuda_fp16.h>
#include <cstdint>
#include <cstddef>

#define BB 128
#define TT 128
#define HH 1024
#define H3 3072
#define NBY 64     // CTAs per by-group barrier

// Scratch (static device globals -- no dynamic allocation allowed).
__device__ float   g_xp[50331648ULL];          // [T][B][3H] fp32 (192 MB)
__device__ __half  g_whh[2ULL * 3 * HH * HH];  // Wh fp16
__device__ __half  g_wxh[2ULL * 3 * HH * HH];  // Wx fp16
__device__ __half  g_x16[(size_t)BB * TT * HH]; // input fp16
__device__ __half  g_y16[(size_t)BB * TT * HH]; // layer-1 output fp16
__device__ uint8_t g_himg[2][262144];          // h images: [parity][tile(2)x128KB]
__device__ float   g_bias[2 * H3];             // xproj bias: bx+bh (r,z), bx (n)
__device__ unsigned g_bc[2];                   // per-by barrier
__device__ unsigned g_bp[2];

__device__ __forceinline__ uint32_t pack_h2(float x, float y) {
    __half2 h = __floats2half2_rn(x, y);
    return *reinterpret_cast<uint32_t*>(&h);
}

__device__ __forceinline__ void mma_f16(float d[4], const uint32_t a[4], const uint32_t b[2]) {
    asm volatile(
        "mma.sync.aligned.m16n8k16.row.col.f32.f16.f16.f32 "
        "{%0,%1,%2,%3}, {%4,%5,%6,%7}, {%8,%9}, {%0,%1,%2,%3};"
        : "+f"(d[0]), "+f"(d[1]), "+f"(d[2]), "+f"(d[3])
        : "r"(a[0]), "r"(a[1]), "r"(a[2]), "r"(a[3]), "r"(b[0]), "r"(b[1]));
}

__device__ __forceinline__ void ldsm4(uint32_t& r0, uint32_t& r1, uint32_t& r2, uint32_t& r3,
                                      uint32_t addr) {
    asm volatile("ldmatrix.sync.aligned.m8n8.x4.shared.b16 {%0,%1,%2,%3}, [%4];"
                 : "=r"(r0), "=r"(r1), "=r"(r2), "=r"(r3) : "r"(addr));
}

__device__ __forceinline__ void mbar_wait(uint32_t mbar, uint32_t parity) {
    asm volatile(
        "{\n\t.reg .pred P;\n\t"
        "WL_%=:\n\t"
        "mbarrier.try_wait.parity.acquire.cta.shared::cta.b64 P, [%0], %1, 0x989680;\n\t"
        "@P bra.uni WD_%=;\n\t"
        "bra.uni WL_%=;\n\t"
        "WD_%=:\n\t}"
        :: "r"(mbar), "r"(parity) : "memory");
}

// Per-by-group barrier: 64 CTAs (batch halves are independent).
__device__ __forceinline__ void grid_sync_by(int by) {
    __syncthreads();
    if (threadIdx.x == 0) {
        volatile unsigned* vphs = &g_bp[by];
        unsigned ph = *vphs;
        __threadfence();
        unsigned ticket = atomicAdd(&g_bc[by], 1u);
        if (ticket == NBY - 1) {
            *((volatile unsigned*)&g_bc[by]) = 0u;
            __threadfence();
            *vphs = ph + 1u;
        } else {
            while (*vphs == ph) {}
            __threadfence();
        }
    }
    __syncthreads();
}

// ---------------------------------------------------------------------------
__global__ void cvt_f16_kernel(const float* __restrict__ src, __half* __restrict__ dst, int n4)
{
    int i = blockIdx.x * blockDim.x + threadIdx.x;
    if (i < n4) {
        float4 v = ((const float4*)src)[i];
        ((uint2*)dst)[i] = make_uint2(pack_h2(v.x, v.y), pack_h2(v.z, v.w));
    }
}

// h0 (fp32 [B,H]) -> parity-0 h image (fp16, pre-swizzled smem layout).
__global__ void cvt_img_kernel(const float* __restrict__ src)
{
    int i = blockIdx.x * blockDim.x + threadIdx.x;   // chunk id, 16384 total
    int b = i >> 7, c = i & 127;
    int tile = b >> 6, row = b & 63;
    const float* s = src + (size_t)b * HH + c * 8;
    float4 v0 = ((const float4*)s)[0];
    float4 v1 = ((const float4*)s)[1];
    uint4 o;
    o.x = pack_h2(v0.x, v0.y); o.y = pack_h2(v0.z, v0.w);
    o.z = pack_h2(v1.x, v1.y); o.w = pack_h2(v1.z, v1.w);
    int p = c >> 6, c2 = c & 63;
    uint32_t off = (uint32_t)tile * 131072u + (uint32_t)p * 65536u
                 + (uint32_t)row * 1024u + (uint32_t)((c2 ^ (row & 7)) << 4);
    *(uint4*)(&g_himg[0][0] + off) = o;
}

// Combined bias for xproj: bx + bh for gates r,z ; bx only for gate n.
__global__ void bias_kernel(const float* __restrict__ bx, const float* __restrict__ bh,
                            float* __restrict__ out)
{
    int i = blockIdx.x * blockDim.x + threadIdx.x;
    if (i < 2 * H3) {
        int n = i % H3;
        float v = bx[i];
        if (n < 2 * HH) v += bh[i];
        out[i] = v;
    }
}

// ---------------------------------------------------------------------------
// xproj v2: all-fp16 inputs, cp.async 3-stage pipeline.
//   C[m][n] = sum_k A[m][k]*W[n][k] + bias[n];  m = t*B+b, A row at [b,t,:].
//   BM=BN=128, BK=32, 256 threads, 8 warps (2m x 4n), warp 64x32.
//   Stage: A/B tiles 128 rows x 80B (32 halves + 8 pad). 6 stage buffers, 60 KB.
// ---------------------------------------------------------------------------
#define XSTG 10240   // bytes per operand stage
#define XB0  30720   // B stages base

__global__ __launch_bounds__(256) void xproj2_kernel(
    const __half* __restrict__ A16,   // [B,T,H] fp16
    const __half* __restrict__ W16,   // [3H,H] fp16
    const float*  __restrict__ bias, float* __restrict__ xp)
{
    extern __shared__ uint8_t xsm[];  // 61440 B
    const uint32_t smb = (uint32_t)__cvta_generic_to_shared(xsm);

    const int tid  = threadIdx.x;
    const int lane = tid & 31;
    const int wid  = tid >> 5;
    const int wm   = (wid >> 2) * 64;
    const int wn   = (wid & 3) * 32;
    const int m0   = blockIdx.y * 128;
    const int n0   = blockIdx.x * 128;

    // Loader: 1024 x 16B chunks per stage (512 A + 512 B), 4 per thread.
    const __half* gsrc[4]; uint32_t sdst[4];
    #pragma unroll
    for (int j = 0; j < 4; j++) {
        int idx = tid + j * 256;
        if (idx < 512) {
            int row = idx >> 2, kv = idx & 3;
            int m = m0 + row;
            int b = m & (BB - 1);
            int t = m >> 7;
            gsrc[j] = A16 + ((size_t)b * TT + t) * HH + kv * 8;
            sdst[j] = (uint32_t)(row * 80 + kv * 16);
        } else {
            int i2 = idx - 512;
            int row = i2 >> 2, kv = i2 & 3;
            gsrc[j] = W16 + (size_t)(n0 + row) * HH + kv * 8;
            sdst[j] = (uint32_t)(XB0 + row * 80 + kv * 16);
        }
    }

    // Prologue: stages 0,1.
    #pragma unroll
    for (int s = 0; s < 2; s++) {
        #pragma unroll
        for (int j = 0; j < 4; j++)
            asm volatile("cp.async.cg.shared.global [%0], [%1], 16;"
                         :: "r"(smb + (uint32_t)s * XSTG + sdst[j]), "l"(gsrc[j] + s * 32));
        asm volatile("cp.async.commit_group;");
    }

    float acc[4][4][4];
    #pragma unroll
    for (int a = 0; a < 4; a++)
        #pragma unroll
        for (int b = 0; b < 4; b++)
            #pragma unroll
            for (int c = 0; c < 4; c++) acc[a][b][c] = 0.f;

    const int g  = lane >> 3;
    const int r8 = lane & 7;
    const uint32_t aRow = (uint32_t)(((g & 1) * 8 + r8) * 80 + (g >> 1) * 16);
    const uint32_t bRow = (uint32_t)(((g >> 1) * 8 + r8) * 80 + (g & 1) * 16);

    const int NKT = HH / 32;  // 32
    for (int kt = 0; kt < NKT; kt++) {
        asm volatile("cp.async.wait_group 1;");
        __syncthreads();

        // Issue stage kt+2 (buffer (kt+2)%3 == (kt-1)%3, reads done pre-sync).
        if (kt + 2 < NKT) {
            uint32_t sb = (uint32_t)((kt + 2) % 3) * XSTG;
            #pragma unroll
            for (int j = 0; j < 4; j++)
                asm volatile("cp.async.cg.shared.global [%0], [%1], 16;"
                             :: "r"(smb + sb + sdst[j]), "l"(gsrc[j] + (kt + 2) * 32));
        }
        asm volatile("cp.async.commit_group;");

        const uint32_t aB = smb + (uint32_t)(kt % 3) * XSTG;
        const uint32_t bB = aB + XB0;
        #pragma unroll
        for (int kk = 0; kk < 2; kk++) {
            uint32_t kb = (uint32_t)kk * 32;
            uint32_t af[4][4], bf[2][4];
            #pragma unroll
            for (int mt = 0; mt < 4; mt++)
                ldsm4(af[mt][0], af[mt][1], af[mt][2], af[mt][3],
                      aB + (uint32_t)(wm + mt * 16) * 80 + aRow + kb);
            #pragma unroll
            for (int nb2 = 0; nb2 < 2; nb2++)
                ldsm4(bf[nb2][0], bf[nb2][1], bf[nb2][2], bf[nb2][3],
                      bB + (uint32_t)(wn + nb2 * 16) * 80 + bRow + kb);
            #pragma unroll
            for (int mt = 0; mt < 4; mt++)
                #pragma unroll
                for (int nb2 = 0; nb2 < 2; nb2++) {
                    mma_f16(acc[mt][nb2 * 2],     af[mt], &bf[nb2][0]);
                    mma_f16(acc[mt][nb2 * 2 + 1], af[mt], &bf[nb2][2]);
                }
        }
    }

    // Epilogue: +bias, coalesced store.
    #pragma unroll
    for (int mt = 0; mt < 4; mt++) {
        int r = m0 + wm + mt * 16 + (lane >> 2);
        #pragma unroll
        for (int nt = 0; nt < 4; nt++) {
            int cg = n0 + wn + nt * 8 + (lane & 3) * 2;
            float2 bz = *(const float2*)(bias + cg);
            float2 v0 = make_float2(acc[mt][nt][0] + bz.x, acc[mt][nt][1] + bz.y);
            float2 v1 = make_float2(acc[mt][nt][2] + bz.x, acc[mt][nt][3] + bz.y);
            *(float2*)(xp + (size_t)r * H3 + cg)       = v0;
            *(float2*)(xp + (size_t)(r + 8) * H3 + cg) = v1;
        }
    }
}

// ---------------------------------------------------------------------------
// Persistent recurrence (from R9) + y16 emission + per-by barrier.
//   CTA: 64 batches x 16 units (48 B-rows = unit*3+gate). Grid (64,2)=128.
// ---------------------------------------------------------------------------
#define WOFF 1024
#define HOFF (WOFF + 48 * 2048)          // 99328
#define SMEM_TOT (HOFF + 131072)         // 230400

__global__ __launch_bounds__(384) void persist_kernel(
    const __half* __restrict__ Wh_h,     // fp16 [3,H,H] (layer slice)
    const float*  __restrict__ bhn,      // [H] gate-n hidden bias
    const float*  __restrict__ h0l,      // fp32 [B,H] initial hidden
    const float*  __restrict__ xp,       // [T,B,3H]
    float*        __restrict__ y,        // [B,T,H]
    __half*       __restrict__ y16,      // [B,T,H] fp16 (next layer's input)
    float*        __restrict__ hlast)    // fp32 [B,H] final hidden out
{
    extern __shared__ uint8_t dsm[];
    const uint32_t smbase = (uint32_t)__cvta_generic_to_shared(dsm);
    const int tid  = threadIdx.x;
    const int lane = tid & 31;
    const int wid  = tid >> 5;           // 0..11
    const int o0   = blockIdx.x * 16;    // unit base
    const int by   = blockIdx.y;         // batch tile (0/1)
    const int b0   = by * 64;
    const int wm   = (wid / 3) * 16;     // 0,16,32,48
    const int wn   = (wid % 3) * 16;     // 0,16,32

    // Header: bh_n + two mbarriers.
    if (tid < 16) ((float*)dsm)[tid] = bhn[o0 + tid];
    if (tid == 0) {
        asm volatile("mbarrier.init.shared.b64 [%0], %1;" :: "r"(smbase + 64), "r"(1u) : "memory");
        asm volatile("mbarrier.init.shared.b64 [%0], %1;" :: "r"(smbase + 72), "r"(1u) : "memory");
    }

    // One-time Wh load: 48 rows x 128 chunks(16B). Row r = 3*u + g.
    for (int i = tid; i < 6144; i += 384) {
        int r = i >> 7, c = i & 127;
        int u = r / 3, g = r - 3 * u;
        const __half* src = Wh_h + ((size_t)(g * HH + o0 + u)) * HH + c * 8;
        uint32_t dst = smbase + WOFF + (uint32_t)r * 2048 + (uint32_t)((c ^ (r & 7)) << 4);
        asm volatile("cp.async.cg.shared.global [%0], [%1], 16;" :: "r"(dst), "l"(src));
    }
    asm volatile("cp.async.commit_group;");

    // Epilogue thread mapping: b = tid>>2, u0 = (tid&3)*4.
    const int eb  = tid >> 2;
    const int eu0 = (tid & 3) * 4;
    const int ebg = b0 + eb;
    const int eog = o0 + eu0;
    const uint32_t ecc  = (uint32_t)(eog >> 3);
    const uint32_t eoff = (ecc >> 6) * 65536u + (uint32_t)eb * 1024u
                        + (((ecc & 63u) ^ (uint32_t)(eb & 7)) << 4) + ((uint32_t)(eog & 4) << 1);

    // h carried in registers; init from h0 (fp32, exact).
    float hv[4] = {0.f, 0.f, 0.f, 0.f};
    if (tid < 256) {
        float4 h04 = *(const float4*)(h0l + (size_t)ebg * HH + eog);
        hv[0] = h04.x; hv[1] = h04.y; hv[2] = h04.z; hv[3] = h04.w;
    }

    asm volatile("cp.async.wait_group 0;");
    __syncthreads();

    // Invariant ldsm per-lane bases.
    const int g  = lane >> 3;
    const int r8 = lane & 7;
    const int arow = wm + (g & 1) * 8 + r8;          // h row (batch)
    const int brow = wn + (g >> 1) * 8 + r8;         // Wh row
    const uint32_t aBase0 = smbase + HOFF + (uint32_t)arow * 1024;
    const uint32_t bBase  = smbase + WOFF + (uint32_t)brow * 2048;
    const uint32_t arm = (uint32_t)(arow & 7);
    const uint32_t brm = (uint32_t)(brow & 7);
    const uint32_t ahalf = (uint32_t)(g >> 1);
    const uint32_t bhalf = (uint32_t)(g & 1);

    for (int t = 0; t < TT; t++) {
        // Issue both 64 KB bulk copies of this step's h image.
        if (tid == 0) {
            const uint8_t* src = &g_himg[t & 1][0] + (uint32_t)by * 131072u;
            #pragma unroll
            for (int p = 0; p < 2; p++) {
                uint32_t mb = smbase + 64 + (uint32_t)p * 8;
                asm volatile("mbarrier.arrive.expect_tx.shared.b64 _, [%0], %1;"
                             :: "r"(mb), "r"(65536u) : "memory");
                asm volatile(
                    "cp.async.bulk.shared::cta.global.mbarrier::complete_tx::bytes "
                    "[%0], [%1], %2, [%3];"
                    :: "r"(smbase + HOFF + (uint32_t)p * 65536u),
                       "l"(src + p * 65536), "r"(65536u), "r"(mb) : "memory");
            }
        }

        // Prefetch xp for this step's epilogue (hidden under the GEMM).
        float4 xr4, xz4, xn4;
        if (tid < 256) {
            const float* xpr = xp + (size_t)t * BB * H3 + (size_t)ebg * H3 + eog;
            xr4 = *(const float4*)(xpr);
            xz4 = *(const float4*)(xpr + HH);
            xn4 = *(const float4*)(xpr + 2 * HH);
        }

        float acc[2][4];
        #pragma unroll
        for (int nt = 0; nt < 2; nt++)
            #pragma unroll
            for (int c = 0; c < 4; c++) acc[nt][c] = 0.f;

        // Mainloop: 2 phases x 32 K16. Phase p gated by its mbarrier.
        #pragma unroll 1
        for (int p = 0; p < 2; p++) {
            mbar_wait(smbase + 64 + (uint32_t)p * 8, (uint32_t)(t & 1));
            const uint32_t aB = aBase0 + (uint32_t)p * 65536u;
            #pragma unroll
            for (int kk = 0; kk < 32; kk++) {
                uint32_t q   = 2u * (uint32_t)kk + ahalf;
                uint32_t cbk = 2u * (uint32_t)(p * 32 + kk) + bhalf;
                uint32_t af[4], bf[4];
                ldsm4(af[0], af[1], af[2], af[3], aB + ((q ^ arm) << 4));
                ldsm4(bf[0], bf[1], bf[2], bf[3], bBase + ((cbk ^ brm) << 4));
                mma_f16(acc[0], af, &bf[0]);
                mma_f16(acc[1], af, &bf[2]);
            }
        }
        __syncthreads();   // fragment reads done -> safe to alias h region

        // Scatter accumulators: Cs[64][52] fp32, aliased onto h region.
        float* Cs = (float*)(dsm + HOFF);
        #pragma unroll
        for (int nt = 0; nt < 2; nt++) {
            int r = wm + (lane >> 2);
            int c = wn + nt * 8 + (lane & 3) * 2;
            Cs[r * 52 + c]           = acc[nt][0];
            Cs[r * 52 + c + 1]       = acc[nt][1];
            Cs[(r + 8) * 52 + c]     = acc[nt][2];
            Cs[(r + 8) * 52 + c + 1] = acc[nt][3];
        }
        __syncthreads();

        // Gate fusion: h in registers; write y, y16, next-parity h image.
        if (tid < 256) {
            const float* bhn_s = (const float*)dsm;
            #pragma unroll
            for (int j = 0; j < 4; j++) {
                int u = eu0 + j;
                float hr = Cs[eb * 52 + 3 * u + 0];
                float hz = Cs[eb * 52 + 3 * u + 1];
                float hn = Cs[eb * 52 + 3 * u + 2] + bhn_s[u];
                float r  = 1.f / (1.f + __expf(-(((const float*)&xr4)[j] + hr)));
                float z  = 1.f / (1.f + __expf(-(((const float*)&xz4)[j] + hz)));
                float n  = tanhf(((const float*)&xn4)[j] + r * hn);
                hv[j] = (1.f - z) * n + z * hv[j];
            }
            uint2 hp = make_uint2(pack_h2(hv[0], hv[1]), pack_h2(hv[2], hv[3]));
            *(float4*)(y + ((size_t)ebg * TT + t) * HH + eog) =
                make_float4(hv[0], hv[1], hv[2], hv[3]);
            *(uint2*)(y16 + ((size_t)ebg * TT + t) * HH + eog) = hp;
            *(uint2*)(&g_himg[(t + 1) & 1][0] + (uint32_t)by * 131072u + eoff) = hp;
            if (t == TT - 1)
                *(float4*)(hlast + (size_t)ebg * HH + eog) =
                    make_float4(hv[0], hv[1], hv[2], hv[3]);
        }

        if (t + 1 < TT) grid_sync_by(by);
    }

    __syncthreads();
    if (tid == 0) {
        asm volatile("mbarrier.inval.shared.b64 [%0];" :: "r"(smbase + 64) : "memory");
        asm volatile("mbarrier.inval.shared.b64 [%0];" :: "r"(smbase + 72) : "memory");
    }
}

// ---------------------------------------------------------------------------
extern "C" void kernel_launch(void* const* d_in, const int* in_sizes, int n_in,
                              void* d_out, int out_size)
{
    (void)in_sizes; (void)n_in; (void)out_size;
    const float* x   = (const float*)d_in[0];  // [B,T,H]
    const float* h0  = (const float*)d_in[1];  // [L,B,H]
    const float* Wx  = (const float*)d_in[2];  // [L,3,H,H]
    const float* Wh  = (const float*)d_in[3];  // [L,3,H,H]
    const float* bx  = (const float*)d_in[4];  // [L,3,H]
    const float* bh  = (const float*)d_in[5];  // [L,3,H]
    float* out   = (float*)d_out;              // [B,T,H] then [L,B,H]
    float* hlast = out + (size_t)BB * TT * HH;

    float*  xp  = nullptr;
    __half* whh = nullptr;
    __half* wxh = nullptr;
    __half* x16 = nullptr;
    __half* y16 = nullptr;
    float*  gb  = nullptr;
    cudaGetSymbolAddress((void**)&xp,  g_xp);
    cudaGetSymbolAddress((void**)&whh, g_whh);
    cudaGetSymbolAddress((void**)&wxh, g_wxh);
    cudaGetSymbolAddress((void**)&x16, g_x16);
    cudaGetSymbolAddress((void**)&y16, g_y16);
    cudaGetSymbolAddress((void**)&gb,  g_bias);

    cudaFuncSetAttribute(persist_kernel,
                         cudaFuncAttributeMaxDynamicSharedMemorySize, SMEM_TOT);
    cudaFuncSetAttribute(xproj2_kernel,
                         cudaFuncAttributeMaxDynamicSharedMemorySize, 61440);

    // Pre-convert weights + input to fp16; build combined xproj bias.
    {
        int nw = 2 * 3 * HH * HH / 4;
        cvt_f16_kernel<<<nw / 256, 256>>>(Wh, whh, nw);
        cvt_f16_kernel<<<nw / 256, 256>>>(Wx, wxh, nw);
        int nx = BB * TT * HH / 4;
        cvt_f16_kernel<<<nx / 256, 256>>>(x, x16, nx);
        bias_kernel<<<(2 * H3 + 255) / 256, 256>>>(bx, bh, gb);
    }

    dim3 xgrid(H3 / 128, (BB * TT) / 128);  // (24, 128)
    dim3 pgrid(64, 2);                      // 128 CTAs

    for (int l = 0; l < 2; l++) {
        const __half* A16 = (l == 0) ? x16 : y16;  // layer-1 input / layer-0 output
        xproj2_kernel<<<xgrid, 256, 61440>>>(A16, wxh + (size_t)l * 3 * HH * HH,
                                             gb + (size_t)l * H3, xp);
        cvt_img_kernel<<<64, 256>>>(h0 + (size_t)l * BB * HH);
        persist_kernel<<<pgrid, 384, SMEM_TOT>>>(
            whh + (size_t)l * 3 * HH * HH,
            bh + (size_t)l * H3 + 2 * HH,      // bh_n
            h0 + (size_t)l * BB * HH,
            xp, out, y16,
            hlast + (size_t)l * BB * HH);
    }
}